// round 4
// baseline (speedup 1.0000x reference)
#include <cuda_runtime.h>
#include <cuda_bf16.h>
#include <cstdint>

// Problem constants (fixed by the reference)
#define NN 50000
#define NE 600000
#define NG 64
#define D_IN 128
#define D_HID 128
#define D_OUT 64

// ---------------- device scratch (no allocs allowed) ----------------
__device__ __align__(16) int   g_cnt[NN];        // in-degree incl self loop
__device__ __align__(16) float g_dinv[NN];
__device__ __align__(16) int   g_rowptr[NN + 1];
__device__ __align__(16) int   g_fillptr[NN];
__device__ __align__(16) int   g_bsum[256];
__device__ __align__(16) int   g_boff[256];
__device__ __align__(16) int   g_col[NE];
__device__ __align__(16) float g_hs1[NN * D_HID];   // (x@W1)*dinv[row]
__device__ __align__(16) float g_out1[NN * D_HID];  // relu(layer1 agg)
__device__ __align__(16) float g_hs2[NN * D_OUT];   // (out1@W2)*dinv[row]
__device__ __align__(16) float g_gsum[NG * D_OUT];
__device__ __align__(16) int   g_gcnt[NG];

// ---------------- init ----------------
__global__ void k_init(int n) {
    int i = blockIdx.x * blockDim.x + threadIdx.x;
    if (i < n) g_cnt[i] = 1;                 // self loop
    if (i < NG * D_OUT) g_gsum[i] = 0.0f;
    if (i < NG) g_gcnt[i] = 0;
}

// ---------------- degree ----------------
__global__ void k_deg(const int* __restrict__ ei, int e) {
    int i = blockIdx.x * blockDim.x + threadIdx.x;
    if (i < e) {
        int d = ei[e + i];                   // dst row (int32!)
        atomicAdd(&g_cnt[d], 1);
    }
}

__global__ void k_dinv(int n) {
    int i = blockIdx.x * blockDim.x + threadIdx.x;
    if (i < n) g_dinv[i] = rsqrtf((float)g_cnt[i]);
}

// ---------------- CSR build: scan of (cnt-1) ----------------
__global__ void k_scan1(int n) {
    __shared__ int s[256];
    int t = threadIdx.x, b = blockIdx.x;
    int i = b * 256 + t;
    int v = (i < n) ? (g_cnt[i] - 1) : 0;
    s[t] = v;
    __syncthreads();
    #pragma unroll
    for (int off = 1; off < 256; off <<= 1) {
        int add = (t >= off) ? s[t - off] : 0;
        __syncthreads();
        s[t] += add;
        __syncthreads();
    }
    if (i < n) g_rowptr[i] = s[t] - v;       // block-local exclusive
    if (t == 255) g_bsum[b] = s[255];
}

__global__ void k_scan2(int nb) {
    __shared__ int s[256];
    int t = threadIdx.x;
    int v = (t < nb) ? g_bsum[t] : 0;
    s[t] = v;
    __syncthreads();
    #pragma unroll
    for (int off = 1; off < 256; off <<= 1) {
        int add = (t >= off) ? s[t - off] : 0;
        __syncthreads();
        s[t] += add;
        __syncthreads();
    }
    g_boff[t] = s[t] - v;                    // exclusive block offsets
}

__global__ void k_scan3(int n, int e) {
    int i = blockIdx.x * blockDim.x + threadIdx.x;
    if (i < n) {
        int val = g_rowptr[i] + g_boff[i >> 8];
        g_rowptr[i] = val;
        g_fillptr[i] = val;
    }
    if (i == 0) g_rowptr[n] = e;
}

__global__ void k_fill(const int* __restrict__ ei, int e) {
    int i = blockIdx.x * blockDim.x + threadIdx.x;
    if (i < e) {
        int s = ei[i];
        int d = ei[e + i];
        int pos = atomicAdd(&g_fillptr[d], 1);
        g_col[pos] = s;
    }
}

// ---------------- GEMM: out[r] = (X[r,:] @ W) * dinv[r] ----------------
// X: [M,128] row-major, W: [128,N] row-major, K chunked (KC=32) so static
// smem stays under 48KB. LAYER=1: X=arg, out=g_hs1. LAYER=2: X=g_out1, out=g_hs2.
template <int N, int LAYER>
__global__ __launch_bounds__(256) void k_gemm(const float* __restrict__ Xarg,
                                              const float* __restrict__ W,
                                              int M) {
    constexpr int K  = 128;
    constexpr int KC = 32;           // k chunk
    constexpr int TM = 64;           // rows per block
    constexpr int CG = N / 4;        // col groups of 4 per thread row
    constexpr int TY = 256 / CG;     // thread rows
    constexpr int RPT = TM / TY;     // rows per thread
    constexpr int XP = KC + 4;       // padded X chunk row (36 floats = 144B, 16B mult.)

    __shared__ float Ws[KC * N];     // <=16KB
    __shared__ float Xs[TM * XP];    // 9.2KB

    const float* X = (LAYER == 1) ? Xarg : (const float*)g_out1;
    float*       out = (LAYER == 1) ? g_hs1 : g_hs2;

    int tid = threadIdx.x;
    int tx = tid % CG, ty = tid / CG;
    int row0 = blockIdx.x * TM;

    float acc[RPT][4] = {};
    float4* Ws4 = (float4*)Ws;

    for (int k0 = 0; k0 < K; k0 += KC) {
        // load W chunk [KC][N] via float4
        #pragma unroll
        for (int i = tid; i < KC * N / 4; i += 256) {
            int r = i / (N / 4), c = i % (N / 4);
            Ws4[i] = ((const float4*)W)[(k0 + r) * (N / 4) + c];
        }
        // load X chunk [TM][KC] via float4, padded rows
        #pragma unroll
        for (int i = tid; i < TM * KC / 4; i += 256) {
            int r = i / (KC / 4), c4 = i % (KC / 4);
            int gr = row0 + r;
            float4 v = (gr < M) ? ((const float4*)X)[gr * (K / 4) + (k0 / 4) + c4]
                                : make_float4(0.f, 0.f, 0.f, 0.f);
            *(float4*)&Xs[r * XP + c4 * 4] = v;
        }
        __syncthreads();

        #pragma unroll
        for (int kk = 0; kk < KC; kk += 4) {
            float4 a4[RPT];
            #pragma unroll
            for (int r = 0; r < RPT; r++)
                a4[r] = *(float4*)&Xs[(ty + r * TY) * XP + kk];
            #pragma unroll
            for (int k2 = 0; k2 < 4; k2++) {
                float4 b = Ws4[((kk + k2) * N) / 4 + tx];
                #pragma unroll
                for (int r = 0; r < RPT; r++) {
                    float a = (&a4[r].x)[k2];
                    acc[r][0] = fmaf(a, b.x, acc[r][0]);
                    acc[r][1] = fmaf(a, b.y, acc[r][1]);
                    acc[r][2] = fmaf(a, b.z, acc[r][2]);
                    acc[r][3] = fmaf(a, b.w, acc[r][3]);
                }
            }
        }
        __syncthreads();
    }

    #pragma unroll
    for (int r = 0; r < RPT; r++) {
        int gr = row0 + ty + r * TY;
        if (gr < M) {
            float dv = g_dinv[gr];
            float4 o = make_float4(acc[r][0] * dv, acc[r][1] * dv,
                                   acc[r][2] * dv, acc[r][3] * dv);
            ((float4*)out)[gr * (N / 4) + tx] = o;
        }
    }
}

// ---------------- aggregation: warp per node ----------------
// val = dinv[i] * (hs[i] + sum_{s in N(i)} hs[s]) + bias
// LAYER=1: hs=g_hs1, relu -> g_out1.  LAYER=2: hs=g_hs2, pool -> g_gsum.
template <int DIM, int LAYER>
__global__ __launch_bounds__(256) void k_agg(const float* __restrict__ bias,
                                             const int* __restrict__ batch,
                                             int n) {
    constexpr int V = DIM / 32;
    const float* hs = (LAYER == 1) ? g_hs1 : g_hs2;
    int warp = (blockIdx.x * blockDim.x + threadIdx.x) >> 5;
    int lane = threadIdx.x & 31;
    if (warp >= n) return;
    int node = warp;

    float acc[V];
    const float* selfp = hs + (size_t)node * DIM + lane;
    #pragma unroll
    for (int v = 0; v < V; v++) acc[v] = selfp[32 * v];

    int e = g_rowptr[node];
    int t = g_rowptr[node + 1];
    for (; e + 1 < t; e += 2) {
        int c0 = g_col[e], c1 = g_col[e + 1];
        const float* p0 = hs + (size_t)c0 * DIM + lane;
        const float* p1 = hs + (size_t)c1 * DIM + lane;
        #pragma unroll
        for (int v = 0; v < V; v++) acc[v] += p0[32 * v];
        #pragma unroll
        for (int v = 0; v < V; v++) acc[v] += p1[32 * v];
    }
    if (e < t) {
        int c0 = g_col[e];
        const float* p0 = hs + (size_t)c0 * DIM + lane;
        #pragma unroll
        for (int v = 0; v < V; v++) acc[v] += p0[32 * v];
    }

    float dv = g_dinv[node];
    if (LAYER == 1) {
        #pragma unroll
        for (int v = 0; v < V; v++) {
            float val = fmaf(acc[v], dv, __ldg(&bias[lane + 32 * v]));
            g_out1[(size_t)node * DIM + lane + 32 * v] = fmaxf(val, 0.0f);
        }
    } else {
        int gidx = batch[node];
        #pragma unroll
        for (int v = 0; v < V; v++) {
            float val = fmaf(acc[v], dv, __ldg(&bias[lane + 32 * v]));
            atomicAdd(&g_gsum[gidx * DIM + lane + 32 * v], val);
        }
    }
}

// ---------------- graph counts ----------------
__global__ void k_count(const int* __restrict__ batch, int n) {
    __shared__ int hist[NG];
    int t = threadIdx.x;
    if (t < NG) hist[t] = 0;
    __syncthreads();
    int i = blockIdx.x * blockDim.x + t;
    if (i < n) atomicAdd(&hist[batch[i]], 1);
    __syncthreads();
    if (t < NG && hist[t]) atomicAdd(&g_gcnt[t], hist[t]);
}

// ---------------- final divide ----------------
__global__ void k_final(float* __restrict__ out) {
    int i = blockIdx.x * blockDim.x + threadIdx.x;
    if (i < NG * D_OUT) {
        int g = i / D_OUT;
        float c = (float)max(g_gcnt[g], 1);
        out[i] = g_gsum[i] / c;
    }
}

// ---------------- launch (NO host runtime API calls — graph-capturable) ----
extern "C" void kernel_launch(void* const* d_in, const int* in_sizes, int n_in,
                              void* d_out, int out_size) {
    // Identify inputs by element count (all distinct) — robust to ordering.
    const float* x = nullptr; const int* ei = nullptr; const int* batch = nullptr;
    const float* W1 = nullptr; const float* b1 = nullptr;
    const float* W2 = nullptr; const float* b2 = nullptr;
    for (int i = 0; i < n_in; i++) {
        switch (in_sizes[i]) {
            case NN * D_IN:      x     = (const float*)d_in[i]; break;  // 6,400,000
            case 2 * NE:         ei    = (const int*)d_in[i];   break;  // 1,200,000
            case NN:             batch = (const int*)d_in[i];   break;  // 50,000
            case D_IN * D_HID:   W1    = (const float*)d_in[i]; break;  // 16,384
            case D_HID * D_OUT:  W2    = (const float*)d_in[i]; break;  // 8,192
            case D_HID:          b1    = (const float*)d_in[i]; break;  // 128
            case D_OUT:          b2    = (const float*)d_in[i]; break;  // 64
        }
    }
    float* out = (float*)d_out;               // [64,64]

    const int n = NN, e = NE;
    const int nb256n = (n + 255) / 256;   // 196
    const int nb256e = (e + 255) / 256;

    k_init<<<nb256n, 256>>>(n);
    k_deg<<<nb256e, 256>>>(ei, e);
    k_dinv<<<nb256n, 256>>>(n);
    k_scan1<<<nb256n, 256>>>(n);
    k_scan2<<<1, 256>>>(nb256n);
    k_scan3<<<nb256n, 256>>>(n, e);
    k_fill<<<nb256e, 256>>>(ei, e);

    int gb = (n + 63) / 64;               // 782 GEMM blocks
    k_gemm<128, 1><<<gb, 256>>>(x, W1, n);
    k_agg<128, 1><<<(n + 7) / 8, 256>>>(b1, nullptr, n);
    k_gemm<64, 2><<<gb, 256>>>(nullptr, W2, n);
    k_agg<64, 2><<<(n + 7) / 8, 256>>>(b2, batch, n);
    k_count<<<nb256n, 256>>>(batch, n);
    k_final<<<(NG * D_OUT + 255) / 256, 256>>>(out);
}